// round 1
// baseline (speedup 1.0000x reference)
#include <cuda_runtime.h>

#define SDIM 64
#define NOBJ 256
#define LSEQ 40
#define LID  256
#define PC   128
#define OD   128
#define KNB  17   // k+1 neighbors (k=16 in this problem instance)

// ---------------- device scratch (static, no allocations) ----------------
__device__ float g_f[SDIM * NOBJ * OD];        // feat MLP output  (8 MB)
__device__ float g_lang[SDIM * LSEQ * OD];     // lang MLP output
__device__ int   g_knn[SDIM * NOBJ * KNB];     // kNN indices
__device__ float g_fw1g[PC * OD];              // grouped weights
__device__ float g_fw2g[OD * OD];
__device__ float g_lw1g[LID * OD];
__device__ float g_lw2g[OD * OD];
__device__ float g_rw2g[OD * OD];

// Pack w[Din x Dout] into i-grouped layout:
// dst[(i>>2)*(Dout*4) + j*4 + (i&3)]  -> float4 view: [g*Dout + j] holds w[4g..4g+3][j]
__global__ void pack_kernel(const float* __restrict__ src, int which, int din, int dout) {
    int idx = blockIdx.x * blockDim.x + threadIdx.x;
    if (idx >= din * dout) return;
    float* dst = (which == 0) ? g_fw1g :
                 (which == 1) ? g_fw2g :
                 (which == 2) ? g_lw1g :
                 (which == 3) ? g_lw2g : g_rw2g;
    int i = idx / dout, j = idx % dout;
    dst[(i >> 2) * (dout * 4) + j * 4 + (i & 3)] = src[idx];
}

// ---------------- kNN: one block per sentence ----------------
__global__ __launch_bounds__(NOBJ) void knn_kernel(const float* __restrict__ coord) {
    __shared__ float cs[NOBJ * 3];
    int s = blockIdx.x;
    int n = threadIdx.x;
    for (int i = n; i < NOBJ * 3; i += NOBJ) cs[i] = coord[s * NOBJ * 3 + i];
    __syncthreads();
    float cx = cs[n * 3 + 0], cy = cs[n * 3 + 1], cz = cs[n * 3 + 2];
    float best[KNB];
    int   bidx[KNB];
#pragma unroll
    for (int t = 0; t < KNB; t++) { best[t] = 3.4e38f; bidx[t] = 0; }
    for (int j = 0; j < NOBJ; j++) {
        float dx = cs[j * 3 + 0] - cx;
        float dy = cs[j * 3 + 1] - cy;
        float dz = cs[j * 3 + 2] - cz;
        float d2 = dx * dx + dy * dy + dz * dz;
        if (d2 < best[KNB - 1]) {
            int p = KNB - 1;
            while (p > 0 && best[p - 1] > d2) {
                best[p] = best[p - 1]; bidx[p] = bidx[p - 1]; p--;
            }
            best[p] = d2; bidx[p] = j;
        }
    }
    for (int t = 0; t < KNB; t++) g_knn[(s * NOBJ + n) * KNB + t] = bidx[t];
}

// ---------------- feat MLP: 128 blocks x 128 rows ----------------
__global__ __launch_bounds__(128) void feat_mlp_kernel(const float* __restrict__ x,
                                                       const float* __restrict__ b1,
                                                       const float* __restrict__ b2) {
    extern __shared__ float sm[];
    float* w1s = sm;                 // PC*OD grouped
    float* w2s = w1s + PC * OD;      // OD*OD grouped
    float* xs  = w2s + OD * OD;      // 8*PC
    float* hs  = xs + 8 * PC;        // 8*OD
    int tid = threadIdx.x;
    for (int i = tid; i < PC * OD; i += 128) w1s[i] = g_fw1g[i];
    for (int i = tid; i < OD * OD; i += 128) w2s[i] = g_fw2g[i];
    float b1r = b1[tid], b2r = b2[tid];
    int row0 = blockIdx.x * 128;
    const float4* w1s4 = (const float4*)w1s;
    const float4* w2s4 = (const float4*)w2s;
    const float4* xs4  = (const float4*)xs;
    const float4* hs4  = (const float4*)hs;
    for (int grp = 0; grp < 128; grp += 8) {
        __syncthreads();
#pragma unroll
        for (int r = 0; r < 8; r++)
            xs[r * PC + tid] = x[(row0 + grp + r) * PC + tid];
        __syncthreads();
        float acc[8];
#pragma unroll
        for (int r = 0; r < 8; r++) acc[r] = b1r;
#pragma unroll 4
        for (int g = 0; g < PC / 4; g++) {
            float4 wv = w1s4[g * OD + tid];
#pragma unroll
            for (int r = 0; r < 8; r++) {
                float4 xv = xs4[(r * PC) / 4 + g];
                acc[r] += xv.x * wv.x + xv.y * wv.y + xv.z * wv.z + xv.w * wv.w;
            }
        }
#pragma unroll
        for (int r = 0; r < 8; r++) hs[r * OD + tid] = fmaxf(acc[r], 0.f);
        __syncthreads();
        float acc2[8];
#pragma unroll
        for (int r = 0; r < 8; r++) acc2[r] = b2r;
#pragma unroll 4
        for (int g = 0; g < OD / 4; g++) {
            float4 wv = w2s4[g * OD + tid];
#pragma unroll
            for (int r = 0; r < 8; r++) {
                float4 hv = hs4[(r * OD) / 4 + g];
                acc2[r] += hv.x * wv.x + hv.y * wv.y + hv.z * wv.z + hv.w * wv.w;
            }
        }
#pragma unroll
        for (int r = 0; r < 8; r++)
            g_f[(row0 + grp + r) * OD + tid] = acc2[r];
    }
}

// ---------------- lang MLP: one block per sentence ----------------
__global__ __launch_bounds__(128) void lang_mlp_kernel(const float* __restrict__ x,
                                                       const float* __restrict__ b1,
                                                       const float* __restrict__ b2) {
    extern __shared__ float sm[];
    float* w1s = sm;                  // LID*OD grouped
    float* w2s = w1s + LID * OD;      // OD*OD grouped
    float* xs  = w2s + OD * OD;       // 8*LID
    float* hs  = xs + 8 * LID;        // 8*OD
    int tid = threadIdx.x;
    int s = blockIdx.x;
    for (int i = tid; i < LID * OD; i += 128) w1s[i] = g_lw1g[i];
    for (int i = tid; i < OD * OD; i += 128) w2s[i] = g_lw2g[i];
    float b1r = b1[tid], b2r = b2[tid];
    const float4* w1s4 = (const float4*)w1s;
    const float4* w2s4 = (const float4*)w2s;
    const float4* xs4  = (const float4*)xs;
    const float4* hs4  = (const float4*)hs;
    for (int grp = 0; grp < LSEQ; grp += 8) {
        __syncthreads();
#pragma unroll
        for (int r = 0; r < 8; r++) {
            int row = grp + r;
            xs[r * LID + tid]       = x[(s * LSEQ + row) * LID + tid];
            xs[r * LID + tid + 128] = x[(s * LSEQ + row) * LID + tid + 128];
        }
        __syncthreads();
        float acc[8];
#pragma unroll
        for (int r = 0; r < 8; r++) acc[r] = b1r;
#pragma unroll 4
        for (int g = 0; g < LID / 4; g++) {
            float4 wv = w1s4[g * OD + tid];
#pragma unroll
            for (int r = 0; r < 8; r++) {
                float4 xv = xs4[(r * LID) / 4 + g];
                acc[r] += xv.x * wv.x + xv.y * wv.y + xv.z * wv.z + xv.w * wv.w;
            }
        }
#pragma unroll
        for (int r = 0; r < 8; r++) hs[r * OD + tid] = fmaxf(acc[r], 0.f);
        __syncthreads();
        float acc2[8];
#pragma unroll
        for (int r = 0; r < 8; r++) acc2[r] = b2r;
#pragma unroll 4
        for (int g = 0; g < OD / 4; g++) {
            float4 wv = w2s4[g * OD + tid];
#pragma unroll
            for (int r = 0; r < 8; r++) {
                float4 hv = hs4[(r * OD) / 4 + g];
                acc2[r] += hv.x * wv.x + hv.y * wv.y + hv.z * wv.z + hv.w * wv.w;
            }
        }
#pragma unroll
        for (int r = 0; r < 8; r++)
            g_lang[(s * LSEQ + grp + r) * OD + tid] = acc2[r];
    }
}

// ---------------- main fused kernel ----------------
// grid (NOBJ/8, SDIM), block 256 = 2 centers x 128 channels.
__global__ __launch_bounds__(256) void main_kernel(const float* __restrict__ coord,
                                                   const float* __restrict__ lang_mask,
                                                   const float* __restrict__ rel_w1,
                                                   const float* __restrict__ rel_b1,
                                                   const float* __restrict__ rel_b2,
                                                   float* __restrict__ out,
                                                   float* __restrict__ score) {
    extern __shared__ float sm[];
    float* lang_s = sm;                          // 40*132
    float* w2s    = lang_s + LSEQ * 132;         // OD*OD grouped
    float* cs     = w2s + OD * OD;               // 256*3
    float* mask_s = cs + NOBJ * 3;               // 40
    float* fg_s   = mask_s + LSEQ;               // 2*17*132
    float* h_s    = fg_s + 2 * KNB * 132;        // 2*17*132
    float* att_s  = h_s + 2 * KNB * 132;         // 2*17*44
    float* w_s    = att_s + 2 * KNB * 44;        // 2*40*24
    float* ri_s   = w_s + 2 * LSEQ * 24;         // 2*17*12
    float* wred   = ri_s + 2 * KNB * 12;         // 8
    int*   nb_s   = (int*)(wred + 8);            // 2*32

    int s   = blockIdx.y;
    int tid = threadIdx.x;
    int half = tid >> 7;
    int j    = tid & 127;

    for (int i = tid; i < LSEQ * OD; i += 256) {
        int l = i >> 7, jj = i & 127;
        lang_s[l * 132 + jj] = g_lang[(s * LSEQ + l) * OD + jj];
    }
    for (int i = tid; i < OD * OD; i += 256) w2s[i] = g_rw2g[i];
    for (int i = tid; i < NOBJ * 3; i += 256) cs[i] = coord[s * NOBJ * 3 + i];
    if (tid < LSEQ) mask_s[tid] = lang_mask[s * LSEQ + tid];

    float w1r[10];
#pragma unroll
    for (int i = 0; i < 10; i++) w1r[i] = rel_w1[i * OD + j];
    float b1r = rel_b1[j], b2r = rel_b2[j];
    __syncthreads();

    float* fgH  = fg_s + half * KNB * 132;
    float* hH   = h_s  + half * KNB * 132;
    float* attH = att_s + half * KNB * 44;
    float* wH   = w_s  + half * LSEQ * 24;
    float* riH  = ri_s + half * KNB * 12;
    int*   nbH  = nb_s + half * 32;
    const float4* w2s4 = (const float4*)w2s;

    for (int it = 0; it < 4; it++) {
        int n = blockIdx.x * 8 + it * 2 + half;

        // phase A: neighbor indices + relative-coord features
        if (j < KNB) {
            int t = j;
            int nb = g_knn[(s * NOBJ + n) * KNB + t];
            nbH[t] = nb;
            float cnx = cs[nb * 3 + 0], cny = cs[nb * 3 + 1], cnz = cs[nb * 3 + 2];
            float ccx = cs[n * 3 + 0],  ccy = cs[n * 3 + 1],  ccz = cs[n * 3 + 2];
            float rx = cnx - ccx, ry = cny - ccy, rz = cnz - ccz;
            float dist = sqrtf(rx * rx + ry * ry + rz * rz);
            riH[t * 12 + 0] = cnx; riH[t * 12 + 1] = cny; riH[t * 12 + 2] = cnz;
            riH[t * 12 + 3] = ccx; riH[t * 12 + 4] = ccy; riH[t * 12 + 5] = ccz;
            riH[t * 12 + 6] = rx;  riH[t * 12 + 7] = ry;  riH[t * 12 + 8] = rz;
            riH[t * 12 + 9] = dist;
        }
        __syncthreads();

        // phase B: gather fg rows + rel layer-1
#pragma unroll
        for (int t = 0; t < KNB; t++)
            fgH[t * 132 + j] = g_f[(s * NOBJ + nbH[t]) * OD + j];
#pragma unroll
        for (int t = 0; t < KNB; t++) {
            float a = b1r;
#pragma unroll
            for (int i = 0; i < 10; i++) a += riH[t * 12 + i] * w1r[i];
            hH[t * 132 + j] = fmaxf(a, 0.f);
        }
        __syncthreads();

        // phase C: attention logits + rel layer-2 (register tile of 17)
        for (int p = j; p < KNB * LSEQ; p += 128) {
            int t = p % KNB;
            int l = p / KNB;
            const float4* fg4 = (const float4*)(fgH + t * 132);
            const float4* lg4 = (const float4*)(lang_s + l * 132);
            float a = 0.f;
#pragma unroll 8
            for (int g = 0; g < OD / 4; g++) {
                float4 av = fg4[g], bv = lg4[g];
                a += av.x * bv.x + av.y * bv.y + av.z * bv.z + av.w * bv.w;
            }
            attH[t * 44 + l] = a;
        }
        float rel[KNB];
#pragma unroll
        for (int t = 0; t < KNB; t++) rel[t] = b2r;
#pragma unroll 2
        for (int g = 0; g < OD / 4; g++) {
            float4 wv = w2s4[g * OD + j];
#pragma unroll
            for (int t = 0; t < KNB; t++) {
                float4 hv = ((const float4*)(hH + t * 132))[g];
                rel[t] += hv.x * wv.x + hv.y * wv.y + hv.z * wv.z + hv.w * wv.w;
            }
        }
        __syncthreads();

        // phase D: masked softmax + renorm per neighbor row
        if (j < KNB) {
            int t = j;
            float m = -1e30f;
            for (int l = 0; l < LSEQ; l++) m = fmaxf(m, attH[t * 44 + l]);
            float Z = 0.f, Zm = 0.f;
            for (int l = 0; l < LSEQ; l++) {
                float e = __expf(attH[t * 44 + l] - m);
                Z += e;
                float ew = e * mask_s[l];
                Zm += ew;
                wH[l * 24 + t] = ew;
            }
            float inv = 1.f / (Zm + 1e-7f * Z);
            for (int l = 0; l < LSEQ; l++) wH[l * 24 + t] *= inv;
        }
        __syncthreads();

        // phase E: ins = attn @ lang, combine, write out + score
        float ins[KNB];
#pragma unroll
        for (int t = 0; t < KNB; t++) ins[t] = 0.f;
#pragma unroll 2
        for (int l = 0; l < LSEQ; l++) {
            float lg = lang_s[l * 132 + j];
            const float4* w4 = (const float4*)(wH + l * 24);
            float4 w0 = w4[0], w1v = w4[1], w2v = w4[2], w3v = w4[3];
            float w16 = wH[l * 24 + 16];
            ins[0]  += w0.x  * lg; ins[1]  += w0.y  * lg; ins[2]  += w0.z  * lg; ins[3]  += w0.w  * lg;
            ins[4]  += w1v.x * lg; ins[5]  += w1v.y * lg; ins[6]  += w1v.z * lg; ins[7]  += w1v.w * lg;
            ins[8]  += w2v.x * lg; ins[9]  += w2v.y * lg; ins[10] += w2v.z * lg; ins[11] += w2v.w * lg;
            ins[12] += w3v.x * lg; ins[13] += w3v.y * lg; ins[14] += w3v.z * lg; ins[15] += w3v.w * lg;
            ins[16] += w16   * lg;
        }
        float o = 0.f;
#pragma unroll
        for (int t = 0; t < KNB; t++) o += fgH[t * 132 + j] * ins[t] * rel[t];
        o += g_f[(s * NOBJ + n) * OD + j];
        out[(s * NOBJ + n) * OD + j] = o;

        float v = o;
#pragma unroll
        for (int off = 16; off > 0; off >>= 1) v += __shfl_xor_sync(0xffffffffu, v, off);
        if ((tid & 31) == 0) wred[tid >> 5] = v;
        __syncthreads();
        if (j == 0)
            score[s * NOBJ + n] = wred[half * 4 + 0] + wred[half * 4 + 1] +
                                  wred[half * 4 + 2] + wred[half * 4 + 3];
        __syncthreads();
    }
}

// ---------------- launch ----------------
extern "C" void kernel_launch(void* const* d_in, const int* in_sizes, int n_in,
                              void* d_out, int out_size) {
    const float* feat      = (const float*)d_in[0];
    const float* coord     = (const float*)d_in[1];
    const float* lang_feat = (const float*)d_in[2];
    const float* lang_mask = (const float*)d_in[3];
    const float* rel_w1    = (const float*)d_in[4];
    const float* rel_b1    = (const float*)d_in[5];
    const float* rel_w2    = (const float*)d_in[6];
    const float* rel_b2    = (const float*)d_in[7];
    const float* lang_w1   = (const float*)d_in[8];
    const float* lang_b1   = (const float*)d_in[9];
    const float* lang_w2   = (const float*)d_in[10];
    const float* lang_b2   = (const float*)d_in[11];
    const float* feat_w1   = (const float*)d_in[12];
    const float* feat_b1   = (const float*)d_in[13];
    const float* feat_w2   = (const float*)d_in[14];
    const float* feat_b2   = (const float*)d_in[15];

    float* out   = (float*)d_out;
    float* score = (float*)d_out + (out_size - SDIM * NOBJ);

    const int FEAT_SMEM = (PC * OD + OD * OD + 8 * PC + 8 * OD) * 4;
    const int LANG_SMEM = (LID * OD + OD * OD + 8 * LID + 8 * OD) * 4;
    const int MAIN_SMEM = (LSEQ * 132 + OD * OD + NOBJ * 3 + LSEQ +
                           2 * KNB * 132 + 2 * KNB * 132 + 2 * KNB * 44 +
                           2 * LSEQ * 24 + 2 * KNB * 12 + 8 + 2 * 32) * 4;

    cudaFuncSetAttribute(feat_mlp_kernel, cudaFuncAttributeMaxDynamicSharedMemorySize, FEAT_SMEM);
    cudaFuncSetAttribute(lang_mlp_kernel, cudaFuncAttributeMaxDynamicSharedMemorySize, LANG_SMEM);
    cudaFuncSetAttribute(main_kernel,     cudaFuncAttributeMaxDynamicSharedMemorySize, MAIN_SMEM);

    // pack weights into grouped layouts
    pack_kernel<<<(PC * OD + 255) / 256, 256>>>(feat_w1, 0, PC, OD);
    pack_kernel<<<(OD * OD + 255) / 256, 256>>>(feat_w2, 1, OD, OD);
    pack_kernel<<<(LID * OD + 255) / 256, 256>>>(lang_w1, 2, LID, OD);
    pack_kernel<<<(OD * OD + 255) / 256, 256>>>(lang_w2, 3, OD, OD);
    pack_kernel<<<(OD * OD + 255) / 256, 256>>>(rel_w2, 4, OD, OD);

    knn_kernel<<<SDIM, NOBJ>>>(coord);
    feat_mlp_kernel<<<(SDIM * NOBJ) / 128, 128, FEAT_SMEM>>>(feat, feat_b1, feat_b2);
    lang_mlp_kernel<<<SDIM, 128, LANG_SMEM>>>(lang_feat, lang_b1, lang_b2);

    dim3 grid(NOBJ / 8, SDIM);
    main_kernel<<<grid, 256, MAIN_SMEM>>>(coord, lang_mask, rel_w1, rel_b1, rel_b2, out, score);
}

// round 3
// speedup vs baseline: 1.2413x; 1.2413x over previous
#include <cuda_runtime.h>

#define SDIM 64
#define NOBJ 256
#define LSEQ 40
#define LID  256
#define OD   128
#define KNB  17
#define NROWS (SDIM * NOBJ * KNB)   // 278528

// ---------------- packed f32x2 helpers ----------------
#define FMA2(d, a, b) asm("fma.rn.f32x2 %0, %1, %2, %0;" : "+l"(d) : "l"(a), "l"(b))
#define ADD2(d, a, b) asm("add.rn.f32x2 %0, %1, %2;" : "=l"(d) : "l"(a), "l"(b))
#define PACK2(d, lo, hi) asm("mov.b64 %0, {%1, %2};" : "=l"(d) : "f"(lo), "f"(hi))
#define UNPACK2(lo, hi, s) asm("mov.b64 {%0, %1}, %2;" : "=f"(lo), "=f"(hi) : "l"(s))

// ---------------- device scratch (16B aligned where vector-accessed) ----------------
__device__ __align__(16) float g_f[SDIM * NOBJ * OD];
__device__ __align__(16) float g_t1[SDIM * NOBJ * OD];
__device__ __align__(16) float g_lang[SDIM * LSEQ * OD];
__device__ __align__(16) float g_t2[SDIM * LSEQ * OD];
__device__ __align__(16) float g_rel[(size_t)NROWS * OD];   // 142.6 MB
__device__ __align__(16) float g_ri[NROWS * 10];
__device__ int   g_knn[NROWS];
__device__ __align__(16) float g_fw1pk[128 * 128];
__device__ __align__(16) float g_fw2pk[128 * 128];
__device__ __align__(16) float g_lw1pk[256 * 128];
__device__ __align__(16) float g_lw2pk[128 * 128];
__device__ __align__(16) float g_rw2pk[128 * 128];

__device__ __forceinline__ void gbar(int id) {
    asm volatile("bar.sync %0, %1;" :: "r"(id), "r"(128) : "memory");
}

// Pack W[IN x 128] into pair layout: float4 dst[g*64+p] = (W[2g][2p], W[2g][2p+1], W[2g+1][2p], W[2g+1][2p+1])
__global__ void packw_kernel(const float* __restrict__ src, float* __restrict__ dst, int in_dim) {
    int idx = blockIdx.x * blockDim.x + threadIdx.x;
    if (idx >= (in_dim / 2) * 64) return;
    int g = idx >> 6, p = idx & 63;
    float4 v;
    v.x = src[(2 * g) * 128 + 2 * p];
    v.y = src[(2 * g) * 128 + 2 * p + 1];
    v.z = src[(2 * g + 1) * 128 + 2 * p];
    v.w = src[(2 * g + 1) * 128 + 2 * p + 1];
    ((float4*)dst)[idx] = v;
}

// ---------------- kNN + rel-input features ----------------
__global__ __launch_bounds__(NOBJ) void knn_kernel(const float* __restrict__ coord) {
    __shared__ float cs[NOBJ * 3];
    int s = blockIdx.x;
    int n = threadIdx.x;
    for (int i = n; i < NOBJ * 3; i += NOBJ) cs[i] = coord[s * NOBJ * 3 + i];
    __syncthreads();
    float cx = cs[n * 3 + 0], cy = cs[n * 3 + 1], cz = cs[n * 3 + 2];
    float best[KNB];
    int   bidx[KNB];
#pragma unroll
    for (int t = 0; t < KNB; t++) { best[t] = 3.4e38f; bidx[t] = 0; }
    for (int j = 0; j < NOBJ; j++) {
        float dx = cs[j * 3 + 0] - cx;
        float dy = cs[j * 3 + 1] - cy;
        float dz = cs[j * 3 + 2] - cz;
        float d2 = dx * dx + dy * dy + dz * dz;
        if (d2 < best[KNB - 1]) {
            int p = KNB - 1;
            while (p > 0 && best[p - 1] > d2) {
                best[p] = best[p - 1]; bidx[p] = bidx[p - 1]; p--;
            }
            best[p] = d2; bidx[p] = j;
        }
    }
#pragma unroll
    for (int t = 0; t < KNB; t++) {
        int row = (s * NOBJ + n) * KNB + t;
        int nb = bidx[t];
        g_knn[row] = nb;
        float cnx = cs[nb * 3 + 0], cny = cs[nb * 3 + 1], cnz = cs[nb * 3 + 2];
        float rx = cnx - cx, ry = cny - cy, rz = cnz - cz;
        float dist = sqrtf(rx * rx + ry * ry + rz * rz);
        float* ri = g_ri + row * 10;
        ri[0] = cnx; ri[1] = cny; ri[2] = cnz;
        ri[3] = cx;  ri[4] = cy;  ri[5] = cz;
        ri[6] = rx;  ri[7] = ry;  ri[8] = rz;
        ri[9] = dist;
    }
}

// ---------------- generic f32x2 dense layer: Y[R][128] = act(X[R][IN] @ W + b) ----------------
// block 256 threads, 32 rows per block. Wpk in smem, X duplicate-packed in smem.
template<int IN, bool RELU>
__global__ __launch_bounds__(256) void dense_kernel(const float* __restrict__ X,
                                                    const float* __restrict__ Wpk,
                                                    const float* __restrict__ bias,
                                                    float* __restrict__ Y) {
    extern __shared__ float sm[];
    float* wpk  = sm;                       // IN*128 floats
    float* xdup = wpk + IN * 128;           // 32 * IN * 2 floats
    int tid = threadIdx.x;
    for (int i = tid; i < IN * 32; i += 256)
        ((float4*)wpk)[i] = ((const float4*)Wpk)[i];
    int row0 = blockIdx.x * 32;
    for (int idx = tid; idx < 32 * IN; idx += 256) {
        int r = idx / IN, i = idx % IN;
        float x = X[(row0 + r) * IN + i];
        ((float2*)xdup)[r * IN + i] = make_float2(x, x);
    }
    int p = tid & 63, rslot = tid >> 6;
    int rbase = rslot * 8;
    float2 bb = ((const float2*)bias)[p];
    unsigned long long binit; PACK2(binit, bb.x, bb.y);
    __syncthreads();

    unsigned long long acc[8];
#pragma unroll
    for (int r = 0; r < 8; r++) acc[r] = binit;
    const ulonglong2* wq2 = (const ulonglong2*)wpk;
#pragma unroll 2
    for (int g = 0; g < IN / 2; g++) {
        ulonglong2 wq = wq2[g * 64 + p];
#pragma unroll
        for (int r = 0; r < 8; r++) {
            ulonglong2 hq = ((const ulonglong2*)(xdup + (rbase + r) * IN * 2))[g];
            FMA2(acc[r], wq.x, hq.x);
            FMA2(acc[r], wq.y, hq.y);
        }
    }
#pragma unroll
    for (int r = 0; r < 8; r++) {
        float y0, y1; UNPACK2(y0, y1, acc[r]);
        if (RELU) { y0 = fmaxf(y0, 0.f); y1 = fmaxf(y1, 0.f); }
        ((float2*)Y)[(row0 + rbase + r) * 64 + p] = make_float2(y0, y1);
    }
}

// ---------------- fused rel MLP: ri[10] -> 128 -> 128, writes g_rel ----------------
// block 256 threads, 32 rows/iter, 4 iters -> 128 rows/block; grid 2176.
__global__ __launch_bounds__(256) void rel_kernel(const float* __restrict__ rel_w1,
                                                  const float* __restrict__ rel_b1,
                                                  const float* __restrict__ rel_b2) {
    extern __shared__ float sm[];
    float* w2pk = sm;                       // 128*128
    float* hdup = w2pk + 128 * 128;         // 32*256
    float* ris  = hdup + 32 * 256;          // 32*10
    int tid = threadIdx.x;
    for (int i = tid; i < 128 * 32; i += 256)
        ((float4*)w2pk)[i] = ((const float4*)g_rw2pk)[i];
    int c = tid & 127;
    float w1c[10];
#pragma unroll
    for (int i = 0; i < 10; i++) w1c[i] = rel_w1[i * 128 + c];
    float b1c = rel_b1[c];
    int p = tid & 63, rslot = tid >> 6;
    int rbase = rslot * 8;
    float2 bb = ((const float2*)rel_b2)[p];
    unsigned long long binit; PACK2(binit, bb.x, bb.y);
    const ulonglong2* wq2 = (const ulonglong2*)w2pk;

    for (int it = 0; it < 4; it++) {
        int row0 = blockIdx.x * 128 + it * 32;
        __syncthreads();
        for (int idx = tid; idx < 320; idx += 256)
            ris[idx] = g_ri[row0 * 10 + idx];
        __syncthreads();
        // layer 1: c fixed, rows split in halves of 16
        int rh = tid >> 7;
#pragma unroll 4
        for (int rr = 0; rr < 16; rr++) {
            int r = rh * 16 + rr;
            float a = b1c;
#pragma unroll
            for (int i = 0; i < 10; i++) a += ris[r * 10 + i] * w1c[i];
            a = fmaxf(a, 0.f);
            ((float2*)hdup)[r * 128 + c] = make_float2(a, a);
        }
        __syncthreads();
        // layer 2 (f32x2)
        unsigned long long acc[8];
#pragma unroll
        for (int r = 0; r < 8; r++) acc[r] = binit;
#pragma unroll 2
        for (int g = 0; g < 64; g++) {
            ulonglong2 wq = wq2[g * 64 + p];
#pragma unroll
            for (int r = 0; r < 8; r++) {
                ulonglong2 hq = ((const ulonglong2*)(hdup + (rbase + r) * 256))[g];
                FMA2(acc[r], wq.x, hq.x);
                FMA2(acc[r], wq.y, hq.y);
            }
        }
#pragma unroll
        for (int r = 0; r < 8; r++) {
            float y0, y1; UNPACK2(y0, y1, acc[r]);
            ((float2*)g_rel)[(size_t)(row0 + rbase + r) * 64 + p] = make_float2(y0, y1);
        }
    }
}

// ---------------- main fused attention kernel ----------------
// grid (NOBJ/4, SDIM), block 512 = 4 groups x 128 channels; named barrier per group.
// Per-group slab: fg 2244 | att 748 | w 960 | sred 8 | nb 24  -> GSTRIDE 3984 floats
#define GSTRIDE 3984
__global__ __launch_bounds__(512) void main_kernel(const float* __restrict__ lang_mask,
                                                   float* __restrict__ out,
                                                   float* __restrict__ score) {
    extern __shared__ float sm[];
    float* lang_s = sm;                       // 40*132
    float* mask_s = lang_s + LSEQ * 132;      // 40
    float* grp0   = mask_s + LSEQ;

    int s   = blockIdx.y;
    int tid = threadIdx.x;
    int group = tid >> 7;
    int j     = tid & 127;
    int n = blockIdx.x * 4 + group;

    for (int i = tid; i < LSEQ * OD; i += 512) {
        int l = i >> 7, jj = i & 127;
        lang_s[l * 132 + jj] = g_lang[(s * LSEQ + l) * OD + jj];
    }
    if (tid < LSEQ) mask_s[tid] = lang_mask[s * LSEQ + tid];
    __syncthreads();

    float* G    = grp0 + group * GSTRIDE;
    float* fgH  = G;                 // 17*132 = 2244
    float* attH = fgH + 2244;        // 17*44  = 748
    float* wH   = attH + 748;        // 40*24  = 960
    float* sred = wH + 960;          // 8
    int*   nbH  = (int*)(sred + 8);  // 24 slots (17 used)

    int bid = group + 1;

    // phase A: neighbor indices
    if (j < KNB) nbH[j] = g_knn[(s * NOBJ + n) * KNB + j];
    gbar(bid);

    // phase B: gather fg rows, rel values, center f
    float relv[KNB];
#pragma unroll
    for (int t = 0; t < KNB; t++)
        fgH[t * 132 + j] = g_f[(s * NOBJ + nbH[t]) * OD + j];
#pragma unroll
    for (int t = 0; t < KNB; t++)
        relv[t] = g_rel[((size_t)((s * NOBJ + n) * KNB + t)) * OD + j];
    float fcen = g_f[(s * NOBJ + n) * OD + j];
    gbar(bid);

    // phase C: attention logits (f32x2, 4 partial accumulators)
    for (int p = j; p < KNB * LSEQ; p += 128) {
        int t = p % KNB;
        int l = p / KNB;
        const ulonglong2* fgq = (const ulonglong2*)(fgH + t * 132);
        const ulonglong2* lgq = (const ulonglong2*)(lang_s + l * 132);
        unsigned long long a0 = 0, a1 = 0, a2 = 0, a3 = 0;
#pragma unroll
        for (int g = 0; g < 32; g += 4) {
            ulonglong2 x0 = fgq[g],     y0 = lgq[g];
            ulonglong2 x1 = fgq[g + 1], y1 = lgq[g + 1];
            ulonglong2 x2 = fgq[g + 2], y2 = lgq[g + 2];
            ulonglong2 x3 = fgq[g + 3], y3 = lgq[g + 3];
            FMA2(a0, x0.x, y0.x); FMA2(a0, x0.y, y0.y);
            FMA2(a1, x1.x, y1.x); FMA2(a1, x1.y, y1.y);
            FMA2(a2, x2.x, y2.x); FMA2(a2, x2.y, y2.y);
            FMA2(a3, x3.x, y3.x); FMA2(a3, x3.y, y3.y);
        }
        unsigned long long t01, t23, tt;
        ADD2(t01, a0, a1); ADD2(t23, a2, a3); ADD2(tt, t01, t23);
        float lo, hi; UNPACK2(lo, hi, tt);
        attH[t * 44 + l] = lo + hi;
    }
    gbar(bid);

    // phase D: masked softmax + renorm per neighbor row
    if (j < KNB) {
        int t = j;
        float m = -1e30f;
        for (int l = 0; l < LSEQ; l++) m = fmaxf(m, attH[t * 44 + l]);
        float Z = 0.f, Zm = 0.f;
        for (int l = 0; l < LSEQ; l++) {
            float e = __expf(attH[t * 44 + l] - m);
            Z += e;
            float ew = e * mask_s[l];
            Zm += ew;
            wH[l * 24 + t] = ew;
        }
        float inv = 1.f / (Zm + 1e-7f * Z);
        for (int l = 0; l < LSEQ; l++) wH[l * 24 + t] *= inv;
    }
    gbar(bid);

    // phase E: ins = attn @ lang (f32x2 over t-pairs), combine, reduce
    unsigned long long ip[8];
#pragma unroll
    for (int r = 0; r < 8; r++) ip[r] = 0ull;
    float i16 = 0.f;
#pragma unroll 2
    for (int l = 0; l < LSEQ; l++) {
        float lg = lang_s[l * 132 + j];
        unsigned long long lgd; PACK2(lgd, lg, lg);
        const ulonglong2* wq = (const ulonglong2*)(wH + l * 24);
        ulonglong2 wA = wq[0], wB = wq[1];
        FMA2(ip[0], wA.x, lgd); FMA2(ip[1], wA.y, lgd);
        FMA2(ip[2], wB.x, lgd); FMA2(ip[3], wB.y, lgd);
        ulonglong2 wC = wq[2], wD = wq[3];
        FMA2(ip[4], wC.x, lgd); FMA2(ip[5], wC.y, lgd);
        FMA2(ip[6], wD.x, lgd); FMA2(ip[7], wD.y, lgd);
        i16 += wH[l * 24 + 16] * lg;
    }
    float o = 0.f;
#pragma unroll
    for (int r = 0; r < 8; r++) {
        float u, v; UNPACK2(u, v, ip[r]);
        o += fgH[(2 * r) * 132 + j] * u * relv[2 * r];
        o += fgH[(2 * r + 1) * 132 + j] * v * relv[2 * r + 1];
    }
    o += fgH[16 * 132 + j] * i16 * relv[16];
    o += fcen;
    out[(s * NOBJ + n) * OD + j] = o;

    float v = o;
#pragma unroll
    for (int off = 16; off > 0; off >>= 1) v += __shfl_xor_sync(0xffffffffu, v, off);
    if ((j & 31) == 0) sred[j >> 5] = v;
    gbar(bid);
    if (j == 0)
        score[s * NOBJ + n] = sred[0] + sred[1] + sred[2] + sred[3];
}

// ---------------- launch ----------------
extern "C" void kernel_launch(void* const* d_in, const int* in_sizes, int n_in,
                              void* d_out, int out_size) {
    const float* feat      = (const float*)d_in[0];
    const float* coord     = (const float*)d_in[1];
    const float* lang_feat = (const float*)d_in[2];
    const float* lang_mask = (const float*)d_in[3];
    const float* rel_w1    = (const float*)d_in[4];
    const float* rel_b1    = (const float*)d_in[5];
    const float* rel_w2    = (const float*)d_in[6];
    const float* rel_b2    = (const float*)d_in[7];
    const float* lang_w1   = (const float*)d_in[8];
    const float* lang_b1   = (const float*)d_in[9];
    const float* lang_w2   = (const float*)d_in[10];
    const float* lang_b2   = (const float*)d_in[11];
    const float* feat_w1   = (const float*)d_in[12];
    const float* feat_b1   = (const float*)d_in[13];
    const float* feat_w2   = (const float*)d_in[14];
    const float* feat_b2   = (const float*)d_in[15];

    float* out   = (float*)d_out;
    float* score = (float*)d_out + (out_size - SDIM * NOBJ);

    float* d_fw1pk; cudaGetSymbolAddress((void**)&d_fw1pk, g_fw1pk);
    float* d_fw2pk; cudaGetSymbolAddress((void**)&d_fw2pk, g_fw2pk);
    float* d_lw1pk; cudaGetSymbolAddress((void**)&d_lw1pk, g_lw1pk);
    float* d_lw2pk; cudaGetSymbolAddress((void**)&d_lw2pk, g_lw2pk);
    float* d_rw2pk; cudaGetSymbolAddress((void**)&d_rw2pk, g_rw2pk);
    float* d_t1;    cudaGetSymbolAddress((void**)&d_t1, g_t1);
    float* d_t2;    cudaGetSymbolAddress((void**)&d_t2, g_t2);
    float* d_f;     cudaGetSymbolAddress((void**)&d_f, g_f);
    float* d_langb; cudaGetSymbolAddress((void**)&d_langb, g_lang);

    const int DENSE128_SMEM = (128 * 128 + 32 * 256) * 4;          // 98304
    const int DENSE256_SMEM = (256 * 128 + 32 * 512) * 4;          // 196608
    const int REL_SMEM      = (128 * 128 + 32 * 256 + 320) * 4;    // 99584
    const int MAIN_SMEM     = (LSEQ * 132 + LSEQ + 4 * GSTRIDE) * 4;   // 85024

    cudaFuncSetAttribute(dense_kernel<128, true>,  cudaFuncAttributeMaxDynamicSharedMemorySize, DENSE128_SMEM);
    cudaFuncSetAttribute(dense_kernel<128, false>, cudaFuncAttributeMaxDynamicSharedMemorySize, DENSE128_SMEM);
    cudaFuncSetAttribute(dense_kernel<256, true>,  cudaFuncAttributeMaxDynamicSharedMemorySize, DENSE256_SMEM);
    cudaFuncSetAttribute(rel_kernel,  cudaFuncAttributeMaxDynamicSharedMemorySize, REL_SMEM);
    cudaFuncSetAttribute(main_kernel, cudaFuncAttributeMaxDynamicSharedMemorySize, MAIN_SMEM);

    // pack weights
    packw_kernel<<<16, 256>>>(feat_w1, d_fw1pk, 128);
    packw_kernel<<<16, 256>>>(feat_w2, d_fw2pk, 128);
    packw_kernel<<<32, 256>>>(lang_w1, d_lw1pk, 256);
    packw_kernel<<<16, 256>>>(lang_w2, d_lw2pk, 128);
    packw_kernel<<<16, 256>>>(rel_w2,  d_rw2pk, 128);

    knn_kernel<<<SDIM, NOBJ>>>(coord);

    // feat MLP
    dense_kernel<128, true ><<<512, 256, DENSE128_SMEM>>>(feat, d_fw1pk, feat_b1, d_t1);
    dense_kernel<128, false><<<512, 256, DENSE128_SMEM>>>(d_t1, d_fw2pk, feat_b2, d_f);
    // lang MLP
    dense_kernel<256, true ><<<80, 256, DENSE256_SMEM>>>(lang_feat, d_lw1pk, lang_b1, d_t2);
    dense_kernel<128, false><<<80, 256, DENSE128_SMEM>>>(d_t2, d_lw2pk, lang_b2, d_langb);
    // rel MLP (fused 2 layers)
    rel_kernel<<<NROWS / 128, 256, REL_SMEM>>>(rel_w1, rel_b1, rel_b2);
    // fused attention + combine
    dim3 grid(NOBJ / 4, SDIM);
    main_kernel<<<grid, 512, MAIN_SMEM>>>(lang_mask, out, score);
}

// round 4
// speedup vs baseline: 1.6357x; 1.3177x over previous
#include <cuda_runtime.h>

#define SDIM 64
#define NOBJ 256
#define LSEQ 40
#define OD   128
#define KNB  17
#define NROWS (SDIM * NOBJ * KNB)   // 278528

// ---------------- packed f32x2 helpers ----------------
#define FMA2(d, a, b) asm("fma.rn.f32x2 %0, %1, %2, %0;" : "+l"(d) : "l"(a), "l"(b))
#define ADD2(d, a, b) asm("add.rn.f32x2 %0, %1, %2;" : "=l"(d) : "l"(a), "l"(b))
#define PACK2(d, lo, hi) asm("mov.b64 %0, {%1, %2};" : "=l"(d) : "f"(lo), "f"(hi))
#define UNPACK2(lo, hi, s) asm("mov.b64 {%0, %1}, %2;" : "=f"(lo), "=f"(hi) : "l"(s))

// ---------------- device scratch ----------------
__device__ __align__(16) float g_f[SDIM * NOBJ * OD];
__device__ __align__(16) float g_t1[SDIM * NOBJ * OD];
__device__ __align__(16) float g_lang[SDIM * LSEQ * OD];
__device__ __align__(16) float g_t2[SDIM * LSEQ * OD];
__device__ __align__(16) float g_rel[(size_t)NROWS * OD];   // 142.6 MB
__device__ __align__(16) float g_ri[NROWS * 10];
__device__ __align__(16) float g_A[SDIM * NOBJ * LSEQ];     // per-sentence f@langT
__device__ int   g_knn[NROWS];

__device__ __forceinline__ void gbar(int id) {
    asm volatile("bar.sync %0, %1;" :: "r"(id), "r"(128) : "memory");
}

// ---------------- kNN + rel-input features ----------------
__global__ __launch_bounds__(NOBJ) void knn_kernel(const float* __restrict__ coord) {
    __shared__ float cs[NOBJ * 3];
    int s = blockIdx.x;
    int n = threadIdx.x;
    for (int i = n; i < NOBJ * 3; i += NOBJ) cs[i] = coord[s * NOBJ * 3 + i];
    __syncthreads();
    float cx = cs[n * 3 + 0], cy = cs[n * 3 + 1], cz = cs[n * 3 + 2];
    float best[KNB];
    int   bidx[KNB];
#pragma unroll
    for (int t = 0; t < KNB; t++) { best[t] = 3.4e38f; bidx[t] = 0; }
    for (int j = 0; j < NOBJ; j++) {
        float dx = cs[j * 3 + 0] - cx;
        float dy = cs[j * 3 + 1] - cy;
        float dz = cs[j * 3 + 2] - cz;
        float d2 = dx * dx + dy * dy + dz * dz;
        if (d2 < best[KNB - 1]) {
            int p = KNB - 1;
            while (p > 0 && best[p - 1] > d2) {
                best[p] = best[p - 1]; bidx[p] = bidx[p - 1]; p--;
            }
            best[p] = d2; bidx[p] = j;
        }
    }
#pragma unroll
    for (int t = 0; t < KNB; t++) {
        int row = (s * NOBJ + n) * KNB + t;
        int nb = bidx[t];
        g_knn[row] = nb;
        float cnx = cs[nb * 3 + 0], cny = cs[nb * 3 + 1], cnz = cs[nb * 3 + 2];
        float rx = cnx - cx, ry = cny - cy, rz = cnz - cz;
        float dist = sqrtf(rx * rx + ry * ry + rz * rz);
        float* ri = g_ri + row * 10;
        ri[0] = cnx; ri[1] = cny; ri[2] = cnz;
        ri[3] = cx;  ri[4] = cy;  ri[5] = cz;
        ri[6] = rx;  ri[7] = ry;  ri[8] = rz;
        ri[9] = dist;
    }
}

// ---------------- 2D-tiled dense layer: Y[R][128] = act(X[R][IN] @ W + b) ----------------
// block 256 threads (16x16); 128 rows x 128 cols per block; thread tile 8x8.
template<int IN, bool RELU>
__global__ __launch_bounds__(256) void gemm_kernel(const float* __restrict__ X,
                                                   const float* __restrict__ W,
                                                   const float* __restrict__ bias,
                                                   float* __restrict__ Y) {
    extern __shared__ float sm[];
    float* ws = sm;              // 128*128 (chunk of W, row-major [k][c])
    float* xs = ws + 128 * 128;  // 128*132 (X chunk transposed [k][r], pad 132)
    int tid = threadIdx.x;
    int tx = tid & 15, ty = tid >> 4;
    int c0 = tx * 8, r0 = ty * 8;
    int row0 = blockIdx.x * 128;

    unsigned long long acc[8][4];
    {
        float2 bv[4];
#pragma unroll
        for (int cp = 0; cp < 4; cp++) bv[cp] = ((const float2*)bias)[tx * 4 + cp];
#pragma unroll
        for (int r = 0; r < 8; r++)
#pragma unroll
            for (int cp = 0; cp < 4; cp++) PACK2(acc[r][cp], bv[cp].x, bv[cp].y);
    }

    for (int kc = 0; kc < IN; kc += 128) {
        __syncthreads();
        // W chunk: contiguous copy
        for (int i = tid; i < 128 * 32; i += 256)
            ((float4*)ws)[i] = ((const float4*)(W + kc * 128))[i];
        // X chunk transposed: [k][r]
        for (int i = tid; i < 128 * 32; i += 256) {
            int r = i >> 5, k4 = i & 31;
            float4 v = *(const float4*)(X + (size_t)(row0 + r) * IN + kc + k4 * 4);
            xs[(k4 * 4 + 0) * 132 + r] = v.x;
            xs[(k4 * 4 + 1) * 132 + r] = v.y;
            xs[(k4 * 4 + 2) * 132 + r] = v.z;
            xs[(k4 * 4 + 3) * 132 + r] = v.w;
        }
        __syncthreads();
#pragma unroll 2
        for (int k = 0; k < 128; k++) {
            float4 xa = *(const float4*)(xs + k * 132 + r0);
            float4 xb = *(const float4*)(xs + k * 132 + r0 + 4);
            ulonglong2 wa = *(const ulonglong2*)(ws + k * 128 + c0);
            ulonglong2 wb = *(const ulonglong2*)(ws + k * 128 + c0 + 4);
            float xr[8] = {xa.x, xa.y, xa.z, xa.w, xb.x, xb.y, xb.z, xb.w};
#pragma unroll
            for (int r = 0; r < 8; r++) {
                unsigned long long xd; PACK2(xd, xr[r], xr[r]);
                FMA2(acc[r][0], wa.x, xd);
                FMA2(acc[r][1], wa.y, xd);
                FMA2(acc[r][2], wb.x, xd);
                FMA2(acc[r][3], wb.y, xd);
            }
        }
    }
#pragma unroll
    for (int r = 0; r < 8; r++) {
        float o[8];
#pragma unroll
        for (int cp = 0; cp < 4; cp++) UNPACK2(o[2 * cp], o[2 * cp + 1], acc[r][cp]);
        if (RELU) {
#pragma unroll
            for (int u = 0; u < 8; u++) o[u] = fmaxf(o[u], 0.f);
        }
        float* yp = Y + (size_t)(row0 + r0 + r) * 128 + c0;
        *(float4*)yp       = make_float4(o[0], o[1], o[2], o[3]);
        *(float4*)(yp + 4) = make_float4(o[4], o[5], o[6], o[7]);
    }
}

// ---------------- fused rel MLP: ri[10] -> 128 -> 128, 2D-tiled l2 ----------------
// block 256 threads, 128 rows per block; grid 2176.
__global__ __launch_bounds__(256) void rel_kernel(const float* __restrict__ rel_w1,
                                                  const float* __restrict__ rel_b1,
                                                  const float* __restrict__ rel_w2,
                                                  const float* __restrict__ rel_b2) {
    extern __shared__ float sm[];
    float* ws  = sm;                 // 128*128 w2 row-major
    float* hs  = ws + 128 * 128;     // 128*132 h transposed [c][r]
    float* w1s = hs + 128 * 132;     // 10*128
    float* ris = w1s + 10 * 128;     // 128*12 (10 used, pad 12)
    int tid = threadIdx.x;
    int row0 = blockIdx.x * 128;

    for (int i = tid; i < 128 * 32; i += 256)
        ((float4*)ws)[i] = ((const float4*)rel_w2)[i];
    for (int i = tid; i < 1280; i += 256) w1s[i] = rel_w1[i];
    for (int i = tid; i < 1280; i += 256) {
        int r = i / 10, ii = i - r * 10;
        ris[r * 12 + ii] = g_ri[(size_t)row0 * 10 + i];
    }
    __syncthreads();

    // layer 1: thread owns column c (128 cols x 2 row-halves), writes hs[c][r]
    {
        int c = tid & 127, rh = tid >> 7;
        float w1c[10];
#pragma unroll
        for (int i = 0; i < 10; i++) w1c[i] = w1s[i * 128 + c];
        float b1c = rel_b1[c];
#pragma unroll 4
        for (int rr = 0; rr < 64; rr++) {
            int r = rh * 64 + rr;
            const float4* rp = (const float4*)(ris + r * 12);
            float4 v0 = rp[0], v1 = rp[1], v2 = rp[2];
            float a = b1c;
            a += v0.x * w1c[0] + v0.y * w1c[1] + v0.z * w1c[2] + v0.w * w1c[3];
            a += v1.x * w1c[4] + v1.y * w1c[5] + v1.z * w1c[6] + v1.w * w1c[7];
            a += v2.x * w1c[8] + v2.y * w1c[9];
            hs[c * 132 + r] = fmaxf(a, 0.f);
        }
    }
    __syncthreads();

    // layer 2: 8x8 register tile per thread
    int tx = tid & 15, ty = tid >> 4;
    int c0 = tx * 8, r0 = ty * 8;
    unsigned long long acc[8][4];
    {
        float2 bv[4];
#pragma unroll
        for (int cp = 0; cp < 4; cp++) bv[cp] = ((const float2*)rel_b2)[tx * 4 + cp];
#pragma unroll
        for (int r = 0; r < 8; r++)
#pragma unroll
            for (int cp = 0; cp < 4; cp++) PACK2(acc[r][cp], bv[cp].x, bv[cp].y);
    }
#pragma unroll 2
    for (int k = 0; k < 128; k++) {
        float4 xa = *(const float4*)(hs + k * 132 + r0);
        float4 xb = *(const float4*)(hs + k * 132 + r0 + 4);
        ulonglong2 wa = *(const ulonglong2*)(ws + k * 128 + c0);
        ulonglong2 wb = *(const ulonglong2*)(ws + k * 128 + c0 + 4);
        float xr[8] = {xa.x, xa.y, xa.z, xa.w, xb.x, xb.y, xb.z, xb.w};
#pragma unroll
        for (int r = 0; r < 8; r++) {
            unsigned long long xd; PACK2(xd, xr[r], xr[r]);
            FMA2(acc[r][0], wa.x, xd);
            FMA2(acc[r][1], wa.y, xd);
            FMA2(acc[r][2], wb.x, xd);
            FMA2(acc[r][3], wb.y, xd);
        }
    }
#pragma unroll
    for (int r = 0; r < 8; r++) {
        float o[8];
#pragma unroll
        for (int cp = 0; cp < 4; cp++) UNPACK2(o[2 * cp], o[2 * cp + 1], acc[r][cp]);
        float* yp = g_rel + (size_t)(row0 + r0 + r) * 128 + c0;
        *(float4*)yp       = make_float4(o[0], o[1], o[2], o[3]);
        *(float4*)(yp + 4) = make_float4(o[4], o[5], o[6], o[7]);
    }
}

// ---------------- per-sentence A = f @ langT : A[s][256][40] ----------------
// grid 64, block 256 (32 n-threads x 8 l-threads); thread tile 8n x 5l.
__global__ __launch_bounds__(256) void attA_kernel() {
    extern __shared__ float sm[];
    float* fT = sm;              // 128 k x 260 (n=256 + pad)
    float* lT = fT + 128 * 260;  // 128 k x 44
    int s = blockIdx.x;
    int tid = threadIdx.x;

    // f transposed: n-fast loop -> conflict-free STS
    for (int i = tid; i < 256 * 32; i += 256) {
        int n = i & 255, k4 = i >> 8;
        float4 v = *(const float4*)(g_f + ((size_t)(s * 256 + n)) * 128 + k4 * 4);
        fT[(k4 * 4 + 0) * 260 + n] = v.x;
        fT[(k4 * 4 + 1) * 260 + n] = v.y;
        fT[(k4 * 4 + 2) * 260 + n] = v.z;
        fT[(k4 * 4 + 3) * 260 + n] = v.w;
    }
    for (int i = tid; i < 40 * 32; i += 256) {
        int l = i % 40, k4 = i / 40;
        float4 v = *(const float4*)(g_lang + ((size_t)(s * 40 + l)) * 128 + k4 * 4);
        lT[(k4 * 4 + 0) * 44 + l] = v.x;
        lT[(k4 * 4 + 1) * 44 + l] = v.y;
        lT[(k4 * 4 + 2) * 44 + l] = v.z;
        lT[(k4 * 4 + 3) * 44 + l] = v.w;
    }
    __syncthreads();

    int tn = tid & 31, tl = tid >> 5;
    int n0 = tn * 8, l0 = tl * 5;
    unsigned long long acc[4][5];
#pragma unroll
    for (int np = 0; np < 4; np++)
#pragma unroll
        for (int u = 0; u < 5; u++) acc[np][u] = 0ull;

#pragma unroll 2
    for (int k = 0; k < 128; k++) {
        float4 fa = *(const float4*)(fT + k * 260 + n0);
        float4 fb = *(const float4*)(fT + k * 260 + n0 + 4);
        unsigned long long f01, f23, f45, f67;
        PACK2(f01, fa.x, fa.y); PACK2(f23, fa.z, fa.w);
        PACK2(f45, fb.x, fb.y); PACK2(f67, fb.z, fb.w);
#pragma unroll
        for (int u = 0; u < 5; u++) {
            float lg = lT[k * 44 + l0 + u];
            unsigned long long ld; PACK2(ld, lg, lg);
            FMA2(acc[0][u], f01, ld);
            FMA2(acc[1][u], f23, ld);
            FMA2(acc[2][u], f45, ld);
            FMA2(acc[3][u], f67, ld);
        }
    }
#pragma unroll
    for (int np = 0; np < 4; np++)
#pragma unroll
        for (int u = 0; u < 5; u++) {
            float a0, a1; UNPACK2(a0, a1, acc[np][u]);
            g_A[((s << 8) + n0 + 2 * np) * 40 + l0 + u]     = a0;
            g_A[((s << 8) + n0 + 2 * np + 1) * 40 + l0 + u] = a1;
        }
}

// ---------------- main fused kernel: gather + softmax + ins + combine ----------------
// grid (NOBJ/4, SDIM), block 512 = 4 groups x 128 channels; named barrier per group.
#define GSTRIDE 3984   // fg 2244 | att 748 | w 960 | sred 8 | nb 24
__global__ __launch_bounds__(512) void main_kernel(const float* __restrict__ lang_mask,
                                                   float* __restrict__ out,
                                                   float* __restrict__ score) {
    extern __shared__ float sm[];
    float* lang_s = sm;                       // 40*132
    float* mask_s = lang_s + LSEQ * 132;      // 40
    float* grp0   = mask_s + LSEQ;

    int s   = blockIdx.y;
    int tid = threadIdx.x;
    int group = tid >> 7;
    int j     = tid & 127;
    int n = blockIdx.x * 4 + group;

    for (int i = tid; i < LSEQ * OD; i += 512) {
        int l = i >> 7, jj = i & 127;
        lang_s[l * 132 + jj] = g_lang[(s * LSEQ + l) * OD + jj];
    }
    if (tid < LSEQ) mask_s[tid] = lang_mask[s * LSEQ + tid];
    __syncthreads();

    float* G    = grp0 + group * GSTRIDE;
    float* fgH  = G;                 // 17*132
    float* attH = fgH + 2244;        // 17*44
    float* wH   = attH + 748;        // 40*24
    float* sred = wH + 960;          // 8
    int*   nbH  = (int*)(sred + 8);  // 24 (17 used)

    int bid = group + 1;

    // phase A: neighbor indices
    if (j < KNB) nbH[j] = g_knn[(s * NOBJ + n) * KNB + j];
    gbar(bid);

    // phase B: gather fg, rel, center f, and logits from g_A
    float relv[KNB];
#pragma unroll
    for (int t = 0; t < KNB; t++)
        fgH[t * 132 + j] = g_f[(s * NOBJ + nbH[t]) * OD + j];
#pragma unroll
    for (int t = 0; t < KNB; t++)
        relv[t] = g_rel[((size_t)((s * NOBJ + n) * KNB + t)) * OD + j];
    float fcen = g_f[(s * NOBJ + n) * OD + j];
    for (int p = j; p < KNB * LSEQ; p += 128) {
        int t = p / LSEQ;
        int l = p - t * LSEQ;
        attH[t * 44 + l] = g_A[((s << 8) + nbH[t]) * 40 + l];
    }
    gbar(bid);

    // phase D: masked softmax + renorm per neighbor row
    if (j < KNB) {
        int t = j;
        float m = -1e30f;
        for (int l = 0; l < LSEQ; l++) m = fmaxf(m, attH[t * 44 + l]);
        float Z = 0.f, Zm = 0.f;
        for (int l = 0; l < LSEQ; l++) {
            float e = __expf(attH[t * 44 + l] - m);
            Z += e;
            float ew = e * mask_s[l];
            Zm += ew;
            wH[l * 24 + t] = ew;
        }
        float inv = 1.f / (Zm + 1e-7f * Z);
        for (int l = 0; l < LSEQ; l++) wH[l * 24 + t] *= inv;
    }
    gbar(bid);

    // phase E: ins = attn @ lang (f32x2 over t-pairs), combine, reduce
    unsigned long long ip[8];
#pragma unroll
    for (int r = 0; r < 8; r++) ip[r] = 0ull;
    float i16 = 0.f;
#pragma unroll 2
    for (int l = 0; l < LSEQ; l++) {
        float lg = lang_s[l * 132 + j];
        unsigned long long lgd; PACK2(lgd, lg, lg);
        const ulonglong2* wq = (const ulonglong2*)(wH + l * 24);
        ulonglong2 wA = wq[0], wB = wq[1];
        FMA2(ip[0], wA.x, lgd); FMA2(ip[1], wA.y, lgd);
        FMA2(ip[2], wB.x, lgd); FMA2(ip[3], wB.y, lgd);
        ulonglong2 wC = wq[2], wD = wq[3];
        FMA2(ip[4], wC.x, lgd); FMA2(ip[5], wC.y, lgd);
        FMA2(ip[6], wD.x, lgd); FMA2(ip[7], wD.y, lgd);
        i16 += wH[l * 24 + 16] * lg;
    }
    float o = 0.f;
#pragma unroll
    for (int r = 0; r < 8; r++) {
        float u, v; UNPACK2(u, v, ip[r]);
        o += fgH[(2 * r) * 132 + j] * u * relv[2 * r];
        o += fgH[(2 * r + 1) * 132 + j] * v * relv[2 * r + 1];
    }
    o += fgH[16 * 132 + j] * i16 * relv[16];
    o += fcen;
    out[(s * NOBJ + n) * OD + j] = o;

    float v = o;
#pragma unroll
    for (int off = 16; off > 0; off >>= 1) v += __shfl_xor_sync(0xffffffffu, v, off);
    if ((j & 31) == 0) sred[j >> 5] = v;
    gbar(bid);
    if (j == 0)
        score[s * NOBJ + n] = sred[0] + sred[1] + sred[2] + sred[3];
}

// ---------------- launch ----------------
extern "C" void kernel_launch(void* const* d_in, const int* in_sizes, int n_in,
                              void* d_out, int out_size) {
    const float* feat      = (const float*)d_in[0];
    const float* coord     = (const float*)d_in[1];
    const float* lang_feat = (const float*)d_in[2];
    const float* lang_mask = (const float*)d_in[3];
    const float* rel_w1    = (const float*)d_in[4];
    const float* rel_b1    = (const float*)d_in[5];
    const float* rel_w2    = (const float*)d_in[6];
    const float* rel_b2    = (const float*)d_in[7];
    const float* lang_w1   = (const float*)d_in[8];
    const float* lang_b1   = (const float*)d_in[9];
    const float* lang_w2   = (const float*)d_in[10];
    const float* lang_b2   = (const float*)d_in[11];
    const float* feat_w1   = (const float*)d_in[12];
    const float* feat_b1   = (const float*)d_in[13];
    const float* feat_w2   = (const float*)d_in[14];
    const float* feat_b2   = (const float*)d_in[15];

    float* out   = (float*)d_out;
    float* score = (float*)d_out + (out_size - SDIM * NOBJ);

    float* d_t1;    cudaGetSymbolAddress((void**)&d_t1, g_t1);
    float* d_t2;    cudaGetSymbolAddress((void**)&d_t2, g_t2);
    float* d_f;     cudaGetSymbolAddress((void**)&d_f, g_f);
    float* d_langb; cudaGetSymbolAddress((void**)&d_langb, g_lang);

    const int GEMM_SMEM = (128 * 128 + 128 * 132) * 4;                       // 133120
    const int REL_SMEM  = (128 * 128 + 128 * 132 + 10 * 128 + 128 * 12) * 4; // 144384
    const int A_SMEM    = (128 * 260 + 128 * 44) * 4;                        // 155648
    const int MAIN_SMEM = (LSEQ * 132 + LSEQ + 4 * GSTRIDE) * 4;             // 85024

    cudaFuncSetAttribute(gemm_kernel<128, true>,  cudaFuncAttributeMaxDynamicSharedMemorySize, GEMM_SMEM);
    cudaFuncSetAttribute(gemm_kernel<128, false>, cudaFuncAttributeMaxDynamicSharedMemorySize, GEMM_SMEM);
    cudaFuncSetAttribute(gemm_kernel<256, true>,  cudaFuncAttributeMaxDynamicSharedMemorySize, GEMM_SMEM);
    cudaFuncSetAttribute(rel_kernel,  cudaFuncAttributeMaxDynamicSharedMemorySize, REL_SMEM);
    cudaFuncSetAttribute(attA_kernel, cudaFuncAttributeMaxDynamicSharedMemorySize, A_SMEM);
    cudaFuncSetAttribute(main_kernel, cudaFuncAttributeMaxDynamicSharedMemorySize, MAIN_SMEM);

    knn_kernel<<<SDIM, NOBJ>>>(coord);

    // feat MLP
    gemm_kernel<128, true ><<<128, 256, GEMM_SMEM>>>(feat, feat_w1, feat_b1, d_t1);
    gemm_kernel<128, false><<<128, 256, GEMM_SMEM>>>(d_t1, feat_w2, feat_b2, d_f);
    // lang MLP
    gemm_kernel<256, true ><<<20, 256, GEMM_SMEM>>>(lang_feat, lang_w1, lang_b1, d_t2);
    gemm_kernel<128, false><<<20, 256, GEMM_SMEM>>>(d_t2, lang_w2, lang_b2, d_langb);
    // per-sentence logit matrix A = f @ langT
    attA_kernel<<<SDIM, 256, A_SMEM>>>();
    // rel MLP (fused 2 layers, 2D-tiled)
    rel_kernel<<<NROWS / 128, 256, REL_SMEM>>>(rel_w1, rel_b1, rel_w2, rel_b2);
    // fused attention gather + softmax + combine
    dim3 grid(NOBJ / 4, SDIM);
    main_kernel<<<grid, 512, MAIN_SMEM>>>(lang_mask, out, score);
}

// round 5
// speedup vs baseline: 2.3701x; 1.4490x over previous
#include <cuda_runtime.h>

#define SDIM 64
#define NOBJ 256
#define LSEQ 40
#define OD   128
#define KNB  17
#define NROWS (SDIM * NOBJ * KNB)   // 278528

typedef unsigned long long ull;

#define FMA2(d, a, b) asm("fma.rn.f32x2 %0, %1, %2, %0;" : "+l"(d) : "l"(a), "l"(b))
#define PACK2(d, lo, hi) asm("mov.b64 %0, {%1, %2};" : "=l"(d) : "f"(lo), "f"(hi))
#define UNPACK2(lo, hi, s) asm("mov.b64 {%0, %1}, %2;" : "=f"(lo), "=f"(hi) : "l"(s))

// ---------------- device scratch ----------------
__device__ __align__(16) float g_f[SDIM * NOBJ * OD];
__device__ __align__(16) float g_t1[SDIM * NOBJ * OD];
__device__ __align__(16) float g_lang[SDIM * LSEQ * OD];
__device__ __align__(16) float g_t2[SDIM * LSEQ * OD];
__device__ __align__(16) float g_rel[(size_t)NROWS * OD];   // 142.6 MB
__device__ __align__(16) float g_ri[NROWS * 10];
__device__ __align__(16) float g_A[SDIM * NOBJ * LSEQ];     // logits per (s, object)
__device__ __align__(16) float g_I[SDIM * NOBJ * OD];       // ins per (s, object)
__device__ int   g_knn[NROWS];

// ---------------- kNN + rel-input features ----------------
__global__ __launch_bounds__(NOBJ) void knn_kernel(const float* __restrict__ coord) {
    __shared__ float cs[NOBJ * 3];
    int s = blockIdx.x;
    int n = threadIdx.x;
    for (int i = n; i < NOBJ * 3; i += NOBJ) cs[i] = coord[s * NOBJ * 3 + i];
    __syncthreads();
    float cx = cs[n * 3 + 0], cy = cs[n * 3 + 1], cz = cs[n * 3 + 2];
    float best[KNB];
    int   bidx[KNB];
#pragma unroll
    for (int t = 0; t < KNB; t++) { best[t] = 3.4e38f; bidx[t] = 0; }
    for (int j = 0; j < NOBJ; j++) {
        float dx = cs[j * 3 + 0] - cx;
        float dy = cs[j * 3 + 1] - cy;
        float dz = cs[j * 3 + 2] - cz;
        float d2 = dx * dx + dy * dy + dz * dz;
        if (d2 < best[KNB - 1]) {
            int p = KNB - 1;
            while (p > 0 && best[p - 1] > d2) {
                best[p] = best[p - 1]; bidx[p] = bidx[p - 1]; p--;
            }
            best[p] = d2; bidx[p] = j;
        }
    }
#pragma unroll
    for (int t = 0; t < KNB; t++) {
        int row = (s * NOBJ + n) * KNB + t;
        int nb = bidx[t];
        g_knn[row] = nb;
        float cnx = cs[nb * 3 + 0], cny = cs[nb * 3 + 1], cnz = cs[nb * 3 + 2];
        float rx = cnx - cx, ry = cny - cy, rz = cnz - cz;
        float dist = sqrtf(rx * rx + ry * ry + rz * rz);
        float* ri = g_ri + row * 10;
        ri[0] = cnx; ri[1] = cny; ri[2] = cnz;
        ri[3] = cx;  ri[4] = cy;  ri[5] = cz;
        ri[6] = rx;  ri[7] = ry;  ri[8] = rz;
        ri[9] = dist;
    }
}

// ---------------- 64-row dense layer: Y[R][128] = act(X[R][IN] @ W + b) ----------------
// block 256 (16x16); 64 rows x 128 cols per block; thread tile 4x8. 2 blocks/SM.
template<int IN, bool RELU>
__global__ __launch_bounds__(256) void gemm64_kernel(const float* __restrict__ X,
                                                     const float* __restrict__ W,
                                                     const float* __restrict__ bias,
                                                     float* __restrict__ Y) {
    extern __shared__ float sm[];
    float* ws = sm;              // 128k x 128c
    float* xs = ws + 128 * 128;  // 128k x 68 (64 rows + pad)
    int tid = threadIdx.x;
    int tx = tid & 15, ty = tid >> 4;
    int c0 = tx * 8, r0 = ty * 4;
    int row0 = blockIdx.x * 64;

    ull acc[4][4];
    {
        float2 bv[4];
#pragma unroll
        for (int cp = 0; cp < 4; cp++) bv[cp] = ((const float2*)bias)[tx * 4 + cp];
#pragma unroll
        for (int r = 0; r < 4; r++)
#pragma unroll
            for (int cp = 0; cp < 4; cp++) PACK2(acc[r][cp], bv[cp].x, bv[cp].y);
    }

    for (int kc = 0; kc < IN; kc += 128) {
        __syncthreads();
        for (int i = tid; i < 128 * 32; i += 256)
            ((float4*)ws)[i] = ((const float4*)(W + kc * 128))[i];
        // transposed X: k-major index, r-minor -> conflict-free STS
        for (int i = tid; i < 32 * 64; i += 256) {
            int k4 = i >> 6, r = i & 63;
            float4 v = *(const float4*)(X + (size_t)(row0 + r) * IN + kc + k4 * 4);
            xs[(k4 * 4 + 0) * 68 + r] = v.x;
            xs[(k4 * 4 + 1) * 68 + r] = v.y;
            xs[(k4 * 4 + 2) * 68 + r] = v.z;
            xs[(k4 * 4 + 3) * 68 + r] = v.w;
        }
        __syncthreads();
#pragma unroll 2
        for (int k = 0; k < 128; k++) {
            float4 xa = *(const float4*)(xs + k * 68 + r0);
            ulonglong2 wa = *(const ulonglong2*)(ws + k * 128 + c0);
            ulonglong2 wb = *(const ulonglong2*)(ws + k * 128 + c0 + 4);
            float xr[4] = {xa.x, xa.y, xa.z, xa.w};
#pragma unroll
            for (int r = 0; r < 4; r++) {
                ull xd; PACK2(xd, xr[r], xr[r]);
                FMA2(acc[r][0], wa.x, xd);
                FMA2(acc[r][1], wa.y, xd);
                FMA2(acc[r][2], wb.x, xd);
                FMA2(acc[r][3], wb.y, xd);
            }
        }
    }
#pragma unroll
    for (int r = 0; r < 4; r++) {
        float o[8];
#pragma unroll
        for (int cp = 0; cp < 4; cp++) UNPACK2(o[2 * cp], o[2 * cp + 1], acc[r][cp]);
        if (RELU) {
#pragma unroll
            for (int u = 0; u < 8; u++) o[u] = fmaxf(o[u], 0.f);
        }
        float* yp = Y + (size_t)(row0 + r0 + r) * 128 + c0;
        *(float4*)yp       = make_float4(o[0], o[1], o[2], o[3]);
        *(float4*)(yp + 4) = make_float4(o[4], o[5], o[6], o[7]);
    }
}

// ---------------- A = f @ langT per half-sentence: A[s][n][40] ----------------
// grid 128 (s x 2 halves), block 256 (32 n-thr x 8 l-thr); tile 4n x 5l.
__global__ __launch_bounds__(256) void attA_kernel() {
    extern __shared__ float sm[];
    float* fT = sm;              // 128k x 132 (128 objects)
    float* lT = fT + 128 * 132;  // 128k x 44
    int s = blockIdx.x >> 1, nh = blockIdx.x & 1;
    int nbase = nh * 128;
    int tid = threadIdx.x;

    for (int i = tid; i < 128 * 32; i += 256) {
        int n = i & 127, k4 = i >> 7;
        float4 v = *(const float4*)(g_f + (size_t)((s << 8) + nbase + n) * 128 + k4 * 4);
        fT[(k4 * 4 + 0) * 132 + n] = v.x;
        fT[(k4 * 4 + 1) * 132 + n] = v.y;
        fT[(k4 * 4 + 2) * 132 + n] = v.z;
        fT[(k4 * 4 + 3) * 132 + n] = v.w;
    }
    for (int i = tid; i < 40 * 32; i += 256) {
        int l = i % 40, k4 = i / 40;
        float4 v = *(const float4*)(g_lang + (size_t)(s * 40 + l) * 128 + k4 * 4);
        lT[(k4 * 4 + 0) * 44 + l] = v.x;
        lT[(k4 * 4 + 1) * 44 + l] = v.y;
        lT[(k4 * 4 + 2) * 44 + l] = v.z;
        lT[(k4 * 4 + 3) * 44 + l] = v.w;
    }
    __syncthreads();

    int tn = tid & 31, tl = tid >> 5;
    int n0 = tn * 4, l0 = tl * 5;
    ull acc[2][5];
#pragma unroll
    for (int np = 0; np < 2; np++)
#pragma unroll
        for (int u = 0; u < 5; u++) acc[np][u] = 0ull;

#pragma unroll 2
    for (int k = 0; k < 128; k++) {
        float4 fa = *(const float4*)(fT + k * 132 + n0);
        ull f01, f23;
        PACK2(f01, fa.x, fa.y); PACK2(f23, fa.z, fa.w);
#pragma unroll
        for (int u = 0; u < 5; u++) {
            float lg = lT[k * 44 + l0 + u];
            ull ld; PACK2(ld, lg, lg);
            FMA2(acc[0][u], f01, ld);
            FMA2(acc[1][u], f23, ld);
        }
    }
#pragma unroll
    for (int np = 0; np < 2; np++)
#pragma unroll
        for (int u = 0; u < 5; u++) {
            float a0, a1; UNPACK2(a0, a1, acc[np][u]);
            g_A[((size_t)((s << 8) + nbase + n0 + 2 * np)) * 40 + l0 + u]     = a0;
            g_A[((size_t)((s << 8) + nbase + n0 + 2 * np + 1)) * 40 + l0 + u] = a1;
        }
}

// ---------------- softmax + I = W @ lang per sentence: I[s][m][128] ----------------
// grid 64, block 512 (32 m-thr x 16 j-thr); tile 8m x 8j.
__global__ __launch_bounds__(512) void insN_kernel(const float* __restrict__ lang_mask) {
    extern __shared__ float sm[];
    float* WT    = sm;               // 40l x 264m
    float* langS = WT + 40 * 264;    // 40l x 128j
    float* mask_s = langS + 40 * 128; // 40
    int s = blockIdx.x;
    int tid = threadIdx.x;

    for (int i = tid; i < 40 * 32; i += 512) {
        int l = i >> 5, j4 = i & 31;
        ((float4*)(langS + l * 128))[j4] = ((const float4*)(g_lang + (size_t)(s * 40 + l) * 128))[j4];
    }
    if (tid < 40) mask_s[tid] = lang_mask[s * 40 + tid];
    for (int i = tid; i < 256 * 40; i += 512) {
        int m = i / 40, l = i % 40;
        WT[l * 264 + m] = g_A[((size_t)(s << 8) + m) * 40 + l];
    }
    __syncthreads();

    // masked softmax + renorm per object m (threads 0..255)
    if (tid < 256) {
        int m = tid;
        float mx = -1e30f;
        for (int l = 0; l < 40; l++) mx = fmaxf(mx, WT[l * 264 + m]);
        float Z = 0.f, Zm = 0.f;
        for (int l = 0; l < 40; l++) {
            float e = __expf(WT[l * 264 + m] - mx);
            Z += e;
            float ew = e * mask_s[l];
            Zm += ew;
            WT[l * 264 + m] = ew;
        }
        float inv = 1.f / (Zm + 1e-7f * Z);
        for (int l = 0; l < 40; l++) WT[l * 264 + m] *= inv;
    }
    __syncthreads();

    // I = W @ lang
    int tx = tid & 15, ty = tid >> 4;
    int j0 = tx * 8, m0 = ty * 8;
    ull acc[8][4];
#pragma unroll
    for (int m = 0; m < 8; m++)
#pragma unroll
        for (int jp = 0; jp < 4; jp++) acc[m][jp] = 0ull;

#pragma unroll 2
    for (int l = 0; l < 40; l++) {
        ulonglong2 la = *(const ulonglong2*)(langS + l * 128 + j0);
        ulonglong2 lb = *(const ulonglong2*)(langS + l * 128 + j0 + 4);
        float4 wa = *(const float4*)(WT + l * 264 + m0);
        float4 wb = *(const float4*)(WT + l * 264 + m0 + 4);
        float wr[8] = {wa.x, wa.y, wa.z, wa.w, wb.x, wb.y, wb.z, wb.w};
#pragma unroll
        for (int m = 0; m < 8; m++) {
            ull wd; PACK2(wd, wr[m], wr[m]);
            FMA2(acc[m][0], la.x, wd);
            FMA2(acc[m][1], la.y, wd);
            FMA2(acc[m][2], lb.x, wd);
            FMA2(acc[m][3], lb.y, wd);
        }
    }
#pragma unroll
    for (int m = 0; m < 8; m++) {
        float o[8];
#pragma unroll
        for (int jp = 0; jp < 4; jp++) UNPACK2(o[2 * jp], o[2 * jp + 1], acc[m][jp]);
        float* yp = g_I + ((size_t)(s << 8) + m0 + m) * 128 + j0;
        *(float4*)yp       = make_float4(o[0], o[1], o[2], o[3]);
        *(float4*)(yp + 4) = make_float4(o[4], o[5], o[6], o[7]);
    }
}

// ---------------- fused rel MLP: ri[10] -> 128 -> 128, k-chunked w2 ----------------
// block 256, 128 rows/block, grid 2176; smem ~112KB -> 2 blocks/SM.
__global__ __launch_bounds__(256) void rel_kernel(const float* __restrict__ rel_w1,
                                                  const float* __restrict__ rel_b1,
                                                  const float* __restrict__ rel_w2,
                                                  const float* __restrict__ rel_b2) {
    extern __shared__ float sm[];
    float* hs  = sm;                 // 128c x 132r (transposed h)
    float* ws  = hs + 128 * 132;     // 64k x 128c chunk of w2
    float* w1s = ws + 64 * 128;      // 10*128
    float* ris = w1s + 1280;         // 128 x 12
    int tid = threadIdx.x;
    int row0 = blockIdx.x * 128;

    for (int i = tid; i < 1280; i += 256) w1s[i] = rel_w1[i];
    for (int i = tid; i < 1280; i += 256) {
        int r = i / 10, ii = i - r * 10;
        ris[r * 12 + ii] = g_ri[(size_t)row0 * 10 + i];
    }
    __syncthreads();

    // layer 1: thread owns hidden channel c, half the rows
    {
        int c = tid & 127, rh = tid >> 7;
        float w1c[10];
#pragma unroll
        for (int i = 0; i < 10; i++) w1c[i] = w1s[i * 128 + c];
        float b1c = rel_b1[c];
#pragma unroll 4
        for (int rr = 0; rr < 64; rr++) {
            int r = rh * 64 + rr;
            const float4* rp = (const float4*)(ris + r * 12);
            float4 v0 = rp[0], v1 = rp[1], v2 = rp[2];
            float a = b1c;
            a += v0.x * w1c[0] + v0.y * w1c[1] + v0.z * w1c[2] + v0.w * w1c[3];
            a += v1.x * w1c[4] + v1.y * w1c[5] + v1.z * w1c[6] + v1.w * w1c[7];
            a += v2.x * w1c[8] + v2.y * w1c[9];
            hs[c * 132 + r] = fmaxf(a, 0.f);
        }
    }

    // layer 2: 8x8 tiles, w2 in two 64-k chunks
    int tx = tid & 15, ty = tid >> 4;
    int c0 = tx * 8, r0 = ty * 8;
    ull acc[8][4];
    {
        float2 bv[4];
#pragma unroll
        for (int cp = 0; cp < 4; cp++) bv[cp] = ((const float2*)rel_b2)[tx * 4 + cp];
#pragma unroll
        for (int r = 0; r < 8; r++)
#pragma unroll
            for (int cp = 0; cp < 4; cp++) PACK2(acc[r][cp], bv[cp].x, bv[cp].y);
    }
    for (int kc = 0; kc < 128; kc += 64) {
        __syncthreads();
        for (int i = tid; i < 64 * 32; i += 256)
            ((float4*)ws)[i] = ((const float4*)(rel_w2 + kc * 128))[i];
        __syncthreads();
#pragma unroll 2
        for (int kk = 0; kk < 64; kk++) {
            int k = kc + kk;
            float4 xa = *(const float4*)(hs + k * 132 + r0);
            float4 xb = *(const float4*)(hs + k * 132 + r0 + 4);
            ulonglong2 wa = *(const ulonglong2*)(ws + kk * 128 + c0);
            ulonglong2 wb = *(const ulonglong2*)(ws + kk * 128 + c0 + 4);
            float xr[8] = {xa.x, xa.y, xa.z, xa.w, xb.x, xb.y, xb.z, xb.w};
#pragma unroll
            for (int r = 0; r < 8; r++) {
                ull xd; PACK2(xd, xr[r], xr[r]);
                FMA2(acc[r][0], wa.x, xd);
                FMA2(acc[r][1], wa.y, xd);
                FMA2(acc[r][2], wb.x, xd);
                FMA2(acc[r][3], wb.y, xd);
            }
        }
    }
#pragma unroll
    for (int r = 0; r < 8; r++) {
        float o[8];
#pragma unroll
        for (int cp = 0; cp < 4; cp++) UNPACK2(o[2 * cp], o[2 * cp + 1], acc[r][cp]);
        float* yp = g_rel + (size_t)(row0 + r0 + r) * 128 + c0;
        *(float4*)yp       = make_float4(o[0], o[1], o[2], o[3]);
        *(float4*)(yp + 4) = make_float4(o[4], o[5], o[6], o[7]);
    }
}

// ---------------- combine: out = sum_t fg * I[idx] * rel + f; score ----------------
// grid 8192, block 256 = 2 centers x 128 channels.
__global__ __launch_bounds__(256) void combine_kernel(float* __restrict__ out,
                                                      float* __restrict__ score) {
    __shared__ int   nb[2][20];
    __shared__ float sred[8];
    int tid = threadIdx.x;
    int half = tid >> 7, j = tid & 127;
    int cidx = blockIdx.x * 2 + half;      // s*256 + n
    if (j < KNB) nb[half][j] = g_knn[cidx * KNB + j];
    __syncthreads();

    int sbase = (cidx >> 8) << 8;
    float acc = g_f[(size_t)cidx * 128 + j];
#pragma unroll
    for (int t = 0; t < KNB; t++) {
        int m = sbase + nb[half][t];
        float fg = g_f[(size_t)m * 128 + j];
        float iv = g_I[(size_t)m * 128 + j];
        float rv = g_rel[((size_t)cidx * KNB + t) * 128 + j];
        acc += fg * iv * rv;
    }
    out[(size_t)cidx * 128 + j] = acc;

    float v = acc;
#pragma unroll
    for (int off = 16; off > 0; off >>= 1) v += __shfl_xor_sync(0xffffffffu, v, off);
    if ((j & 31) == 0) sred[tid >> 5] = v;
    __syncthreads();
    if (j == 0)
        score[cidx] = sred[half * 4 + 0] + sred[half * 4 + 1] +
                      sred[half * 4 + 2] + sred[half * 4 + 3];
}

// ---------------- launch ----------------
extern "C" void kernel_launch(void* const* d_in, const int* in_sizes, int n_in,
                              void* d_out, int out_size) {
    const float* feat      = (const float*)d_in[0];
    const float* coord     = (const float*)d_in[1];
    const float* lang_feat = (const float*)d_in[2];
    const float* lang_mask = (const float*)d_in[3];
    const float* rel_w1    = (const float*)d_in[4];
    const float* rel_b1    = (const float*)d_in[5];
    const float* rel_w2    = (const float*)d_in[6];
    const float* rel_b2    = (const float*)d_in[7];
    const float* lang_w1   = (const float*)d_in[8];
    const float* lang_b1   = (const float*)d_in[9];
    const float* lang_w2   = (const float*)d_in[10];
    const float* lang_b2   = (const float*)d_in[11];
    const float* feat_w1   = (const float*)d_in[12];
    const float* feat_b1   = (const float*)d_in[13];
    const float* feat_w2   = (const float*)d_in[14];
    const float* feat_b2   = (const float*)d_in[15];

    float* out   = (float*)d_out;
    float* score = (float*)d_out + (out_size - SDIM * NOBJ);

    float* d_t1;    cudaGetSymbolAddress((void**)&d_t1, g_t1);
    float* d_t2;    cudaGetSymbolAddress((void**)&d_t2, g_t2);
    float* d_f;     cudaGetSymbolAddress((void**)&d_f, g_f);
    float* d_langb; cudaGetSymbolAddress((void**)&d_langb, g_lang);

    const int GEMM_SMEM = (128 * 128 + 128 * 68) * 4;                    // 100352
    const int ATTA_SMEM = (128 * 132 + 128 * 44) * 4;                    // 90112
    const int INSN_SMEM = (40 * 264 + 40 * 128 + 40) * 4;                // 62880
    const int REL_SMEM  = (128 * 132 + 64 * 128 + 1280 + 128 * 12) * 4;  // 111616

    cudaFuncSetAttribute(gemm64_kernel<128, true>,  cudaFuncAttributeMaxDynamicSharedMemorySize, GEMM_SMEM);
    cudaFuncSetAttribute(gemm64_kernel<128, false>, cudaFuncAttributeMaxDynamicSharedMemorySize, GEMM_SMEM);
    cudaFuncSetAttribute(gemm64_kernel<256, true>,  cudaFuncAttributeMaxDynamicSharedMemorySize, GEMM_SMEM);
    cudaFuncSetAttribute(attA_kernel, cudaFuncAttributeMaxDynamicSharedMemorySize, ATTA_SMEM);
    cudaFuncSetAttribute(insN_kernel, cudaFuncAttributeMaxDynamicSharedMemorySize, INSN_SMEM);
    cudaFuncSetAttribute(rel_kernel,  cudaFuncAttributeMaxDynamicSharedMemorySize, REL_SMEM);

    knn_kernel<<<SDIM, NOBJ>>>(coord);

    // feat MLP (16384 rows)
    gemm64_kernel<128, true ><<<256, 256, GEMM_SMEM>>>(feat, feat_w1, feat_b1, d_t1);
    gemm64_kernel<128, false><<<256, 256, GEMM_SMEM>>>(d_t1, feat_w2, feat_b2, d_f);
    // lang MLP (2560 rows)
    gemm64_kernel<256, true ><<<40, 256, GEMM_SMEM>>>(lang_feat, lang_w1, lang_b1, d_t2);
    gemm64_kernel<128, false><<<40, 256, GEMM_SMEM>>>(d_t2, lang_w2, lang_b2, d_langb);
    // logits per object, softmax + ins per object
    attA_kernel<<<2 * SDIM, 256, ATTA_SMEM>>>();
    insN_kernel<<<SDIM, 512, INSN_SMEM>>>(lang_mask);
    // rel MLP
    rel_kernel<<<NROWS / 128, 256, REL_SMEM>>>(rel_w1, rel_b1, rel_w2, rel_b2);
    // gather-combine
    combine_kernel<<<SDIM * NOBJ / 2, 256>>>(out, score);
}